// round 13
// baseline (speedup 1.0000x reference)
#include <cuda_runtime.h>
#include <cuda_bf16.h>

#define NB 8192
#define NC 32000
#define NC4 (NC / 4)   // 8000 float4 per row
#define ROW_THREADS 256

// Scratch: per-row loss (allocation-free via device global)
__device__ float g_row_loss[NB];

// Robust label fetch: reference declares int64 labels, but JAX without x64
// emits int32. Detect layout from data (high words of int64 < 32000 are 0).
__device__ __forceinline__ int fetch_label(const int* __restrict__ yt32, int row) {
    bool is64 = true;
    #pragma unroll
    for (int k = 1; k < 16; k += 2) {
        if (yt32[k] != 0) { is64 = false; break; }
    }
    int t = is64 ? yt32[2 * row] : yt32[row];
    if (t < 0) t = 0;
    if (t >= NC) t = NC - 1;
    return t;
}

__global__ void __launch_bounds__(ROW_THREADS)
row_loss_kernel(const float* __restrict__ y_pred,
                const int* __restrict__ y_true32) {
    const int row = blockIdx.x;
    const float4* __restrict__ p =
        reinterpret_cast<const float4*>(y_pred + (size_t)row * NC);

    // Prefetch the positive-column logit EARLY (thread 0 only): its latency
    // (label probe + scattered xt load, likely DRAM) is fully hidden behind
    // the ~30us streaming loop instead of sitting on the retirement path.
    float xt = 0.0f;
    if (threadIdx.x == 0) {
        const int t = fetch_label(y_true32, row);
        xt = __ldg(y_pred + (size_t)row * NC + t);
    }

    // Two independent accumulators for ILP / MLP depth.
    // __ldcg: bypass L1 (read-once stream, no reuse), normal L2.
    float s0 = 0.0f, s1 = 0.0f;

    int j = threadIdx.x;
    #pragma unroll 4
    for (; j + ROW_THREADS < NC4; j += 2 * ROW_THREADS) {
        float4 a = __ldcg(&p[j]);
        float4 b = __ldcg(&p[j + ROW_THREADS]);
        s0 += __expf(a.x) + __expf(a.y) + __expf(a.z) + __expf(a.w);
        s1 += __expf(b.x) + __expf(b.y) + __expf(b.z) + __expf(b.w);
    }
    if (j < NC4) {
        float4 a = __ldcg(&p[j]);
        s0 += __expf(a.x) + __expf(a.y) + __expf(a.z) + __expf(a.w);
    }

    // block reduce
    float v = s0 + s1;
    __shared__ float s_part[ROW_THREADS / 32];
    #pragma unroll
    for (int o = 16; o > 0; o >>= 1)
        v += __shfl_down_sync(0xFFFFFFFFu, v, o);
    const int lane = threadIdx.x & 31;
    const int wid  = threadIdx.x >> 5;
    if (lane == 0) s_part[wid] = v;
    __syncthreads();

    if (threadIdx.x == 0) {
        float total = 0.0f;
        #pragma unroll
        for (int w = 0; w < ROW_THREADS / 32; w++) total += s_part[w];

        const float ext = __expf(xt);
        const float sum_neg = total - ext;           // exclude positive column
        g_row_loss[row] = log1pf(sum_neg * __expf(-xt));

        __threadfence();                              // publish before trigger
#if __CUDA_ARCH__ >= 900
        cudaTriggerProgrammaticLaunchCompletion();    // let the reducer fly
#endif
    }
}

__global__ void __launch_bounds__(256)
final_reduce_kernel(float* __restrict__ out) {
#if __CUDA_ARCH__ >= 900
    cudaGridDependencySynchronize();                  // wait for all row triggers
#endif
    // 8192 floats = 2048 float4; 256 threads -> 8 vector loads each, batched.
    const float4* rl4 = reinterpret_cast<const float4*>(g_row_loss);
    float v = 0.0f;
    #pragma unroll 8
    for (int i = threadIdx.x; i < NB / 4; i += 256) {
        float4 a = rl4[i];
        v += (a.x + a.y) + (a.z + a.w);
    }
    __shared__ float s_part[8];
    #pragma unroll
    for (int o = 16; o > 0; o >>= 1)
        v += __shfl_down_sync(0xFFFFFFFFu, v, o);
    const int lane = threadIdx.x & 31;
    const int wid  = threadIdx.x >> 5;
    if (lane == 0) s_part[wid] = v;
    __syncthreads();
    if (wid == 0) {
        v = (lane < 8) ? s_part[lane] : 0.0f;
        #pragma unroll
        for (int o = 4; o > 0; o >>= 1)
            v += __shfl_down_sync(0xFFFFFFFFu, v, o);
        if (lane == 0) out[0] = v * (1.0f / NB);
    }
}

extern "C" void kernel_launch(void* const* d_in, const int* in_sizes, int n_in,
                              void* d_out, int out_size) {
    const float* y_pred   = (const float*)d_in[0];
    const int*   y_true32 = (const int*)d_in[1];
    float*       out      = (float*)d_out;

    row_loss_kernel<<<NB, ROW_THREADS>>>(y_pred, y_true32);

    // Programmatic dependent launch: overlap reducer launch with primary tail.
    cudaLaunchAttribute attr[1];
    attr[0].id = cudaLaunchAttributeProgrammaticStreamSerialization;
    attr[0].val.programmaticStreamSerializationAllowed = 1;

    cudaLaunchConfig_t cfg = {};
    cfg.gridDim  = dim3(1, 1, 1);
    cfg.blockDim = dim3(256, 1, 1);
    cfg.dynamicSmemBytes = 0;
    cfg.stream   = 0;
    cfg.attrs    = attr;
    cfg.numAttrs = 1;

    cudaLaunchKernelEx(&cfg, final_reduce_kernel, out);
}

// round 14
// speedup vs baseline: 1.0156x; 1.0156x over previous
#include <cuda_runtime.h>
#include <cuda_bf16.h>

#define NB 8192
#define NC 32000
#define NC4 (NC / 4)   // 8000 float4 per row
#define ROW_THREADS 256

// Scratch: per-row loss (allocation-free via device global)
__device__ float g_row_loss[NB];

// Robust label fetch: reference declares int64 labels, but JAX without x64
// emits int32. Detect layout from data (high words of int64 < 32000 are 0).
__device__ __forceinline__ int fetch_label(const int* __restrict__ yt32, int row) {
    bool is64 = true;
    #pragma unroll
    for (int k = 1; k < 16; k += 2) {
        if (yt32[k] != 0) { is64 = false; break; }
    }
    int t = is64 ? yt32[2 * row] : yt32[row];
    if (t < 0) t = 0;
    if (t >= NC) t = NC - 1;
    return t;
}

__global__ void __launch_bounds__(ROW_THREADS)
row_loss_kernel(const float* __restrict__ y_pred,
                const int* __restrict__ y_true32) {
    const int row = blockIdx.x;
    const float4* __restrict__ p =
        reinterpret_cast<const float4*>(y_pred + (size_t)row * NC);

    // Prefetch the positive-column logit EARLY (thread 0 only): its latency
    // (label probe + scattered xt load, likely DRAM) is fully hidden behind
    // the ~30us streaming loop instead of sitting on the retirement path.
    float xt = 0.0f;
    if (threadIdx.x == 0) {
        const int t = fetch_label(y_true32, row);
        xt = __ldg(y_pred + (size_t)row * NC + t);
    }

    // Two independent accumulators for ILP / MLP depth.
    // Default .ca loads: L1 coalesces the two float4 per 128B line; measured
    // best vs .cg (152.3) and .cs (152.1).
    float s0 = 0.0f, s1 = 0.0f;

    int j = threadIdx.x;
    #pragma unroll 4
    for (; j + ROW_THREADS < NC4; j += 2 * ROW_THREADS) {
        float4 a = p[j];
        float4 b = p[j + ROW_THREADS];
        s0 += __expf(a.x) + __expf(a.y) + __expf(a.z) + __expf(a.w);
        s1 += __expf(b.x) + __expf(b.y) + __expf(b.z) + __expf(b.w);
    }
    if (j < NC4) {
        float4 a = p[j];
        s0 += __expf(a.x) + __expf(a.y) + __expf(a.z) + __expf(a.w);
    }

    // block reduce
    float v = s0 + s1;
    __shared__ float s_part[ROW_THREADS / 32];
    #pragma unroll
    for (int o = 16; o > 0; o >>= 1)
        v += __shfl_down_sync(0xFFFFFFFFu, v, o);
    const int lane = threadIdx.x & 31;
    const int wid  = threadIdx.x >> 5;
    if (lane == 0) s_part[wid] = v;
    __syncthreads();

    if (threadIdx.x == 0) {
        float total = 0.0f;
        #pragma unroll
        for (int w = 0; w < ROW_THREADS / 32; w++) total += s_part[w];

        const float ext = __expf(xt);
        const float sum_neg = total - ext;           // exclude positive column
        g_row_loss[row] = log1pf(sum_neg * __expf(-xt));

        __threadfence();                              // publish before trigger
#if __CUDA_ARCH__ >= 900
        cudaTriggerProgrammaticLaunchCompletion();    // let the reducer fly
#endif
    }
}

__global__ void __launch_bounds__(256)
final_reduce_kernel(float* __restrict__ out) {
#if __CUDA_ARCH__ >= 900
    cudaGridDependencySynchronize();                  // wait for all row triggers
#endif
    // 8192 floats = 2048 float4; 256 threads -> 8 vector loads each, batched.
    const float4* rl4 = reinterpret_cast<const float4*>(g_row_loss);
    float v = 0.0f;
    #pragma unroll 8
    for (int i = threadIdx.x; i < NB / 4; i += 256) {
        float4 a = rl4[i];
        v += (a.x + a.y) + (a.z + a.w);
    }
    __shared__ float s_part[8];
    #pragma unroll
    for (int o = 16; o > 0; o >>= 1)
        v += __shfl_down_sync(0xFFFFFFFFu, v, o);
    const int lane = threadIdx.x & 31;
    const int wid  = threadIdx.x >> 5;
    if (lane == 0) s_part[wid] = v;
    __syncthreads();
    if (wid == 0) {
        v = (lane < 8) ? s_part[lane] : 0.0f;
        #pragma unroll
        for (int o = 4; o > 0; o >>= 1)
            v += __shfl_down_sync(0xFFFFFFFFu, v, o);
        if (lane == 0) out[0] = v * (1.0f / NB);
    }
}

extern "C" void kernel_launch(void* const* d_in, const int* in_sizes, int n_in,
                              void* d_out, int out_size) {
    const float* y_pred   = (const float*)d_in[0];
    const int*   y_true32 = (const int*)d_in[1];
    float*       out      = (float*)d_out;

    row_loss_kernel<<<NB, ROW_THREADS>>>(y_pred, y_true32);

    // Programmatic dependent launch: overlap reducer launch with primary tail.
    cudaLaunchAttribute attr[1];
    attr[0].id = cudaLaunchAttributeProgrammaticStreamSerialization;
    attr[0].val.programmaticStreamSerializationAllowed = 1;

    cudaLaunchConfig_t cfg = {};
    cfg.gridDim  = dim3(1, 1, 1);
    cfg.blockDim = dim3(256, 1, 1);
    cfg.dynamicSmemBytes = 0;
    cfg.stream   = 0;
    cfg.attrs    = attr;
    cfg.numAttrs = 1;

    cudaLaunchKernelEx(&cfg, final_reduce_kernel, out);
}